// round 1
// baseline (speedup 1.0000x reference)
#include <cuda_runtime.h>
#include <math.h>

// ---------------------------------------------------------------------------
// FFT_Block: global-avg-pool -> SE-style fc(relu)->fc(sigmoid) -> two 1x1
// "spectral" fc heads -> rfft over channels -> amp/phase rescale -> irfft ->
// elementwise multiply. Output [16,384,1,1] fp32.
//
// Heavy part: mean over 128x128 per (b,c)  => one streaming pass over 400MB.
// Everything else: one tiny per-batch block.
// ---------------------------------------------------------------------------

#define B_   16
#define C_   384
#define CH_  64
#define CF_  193
#define HW_  16384   // 128*128

__device__ float g_y0[B_ * C_];   // pooled means, scratch between kernels

// ---------------------------------------------------------------------------
// Kernel 1: global average pool. One block per (b,c). 256 threads, float4.
// ---------------------------------------------------------------------------
__global__ __launch_bounds__(256) void pool_kernel(const float* __restrict__ x) {
    const int bc = blockIdx.x;
    const float4* __restrict__ p =
        reinterpret_cast<const float4*>(x + (size_t)bc * HW_);
    float s = 0.f;
#pragma unroll
    for (int i = 0; i < 16; ++i) {
        float4 v = p[threadIdx.x + 256 * i];
        s += (v.x + v.y) + (v.z + v.w);
    }
#pragma unroll
    for (int o = 16; o > 0; o >>= 1) s += __shfl_down_sync(0xffffffffu, s, o);
    __shared__ float ws[8];
    if ((threadIdx.x & 31) == 0) ws[threadIdx.x >> 5] = s;
    __syncthreads();
    if (threadIdx.x < 8) {
        s = ws[threadIdx.x];
#pragma unroll
        for (int o = 4; o > 0; o >>= 1) s += __shfl_down_sync(0xffu, s, o);
        if (threadIdx.x == 0) g_y0[bc] = s * (1.f / (float)HW_);
    }
}

// ---------------------------------------------------------------------------
// Kernel 2: everything downstream. One block per batch, 384 threads (12 warps).
// ---------------------------------------------------------------------------
__global__ __launch_bounds__(384) void head_kernel(
    const float* __restrict__ W1, const float* __restrict__ b1,
    const float* __restrict__ W2, const float* __restrict__ b2,
    const float* __restrict__ Ws1, const float* __restrict__ bs1,
    const float* __restrict__ Ws2, const float* __restrict__ bs2,
    float* __restrict__ out)
{
    const int b    = blockIdx.x;
    const int t    = threadIdx.x;      // 0..383
    const int w    = t >> 5;           // warp 0..11
    const int lane = t & 31;

    __shared__ float y0s[C_];
    __shared__ float cosT[C_];
    __shared__ float sinT[C_];
    __shared__ float hs[CH_];
    __shared__ float ys[C_];
    __shared__ float rRe[CF_];
    __shared__ float rIm[CF_];

    // load pooled row + build exact twiddle table cos/sin(2*pi*m/384)
    y0s[t] = g_y0[b * C_ + t];
    {
        float ang = (float)t * (6.283185307179586f / (float)C_);
        float sv, cv;
        sincosf(ang, &sv, &cv);
        sinT[t] = sv;
        cosT[t] = cv;
    }
    __syncthreads();

    // h[j] = relu( sum_c y0[c] * W1[j,c,1,1] + b1[j] )   -- warp per j
    for (int j = w; j < CH_; j += 12) {
        float acc = 0.f;
        for (int n = lane; n < C_; n += 32)
            acc += y0s[n] * W1[j * (C_ * 9) + n * 9 + 4];
#pragma unroll
        for (int o = 16; o > 0; o >>= 1) acc += __shfl_down_sync(0xffffffffu, acc, o);
        if (lane == 0) hs[j] = fmaxf(acc + b1[j], 0.f);
    }
    __syncthreads();

    // y[c] = sigmoid( sum_j h[j] * W2[c,j,1,1] + b2[c] ) -- thread per c
    {
        float acc = 0.f;
#pragma unroll
        for (int j = 0; j < CH_; ++j)
            acc += hs[j] * W2[t * (CH_ * 9) + j * 9 + 4];
        acc += b2[t];
        ys[t] = 1.f / (1.f + expf(-acc));
    }
    __syncthreads();

    // For each rfft bin k: DFT + s1 + s2 fused  -- warp per k
    for (int k = w; k < CF_; k += 12) {
        float re = 0.f, im = 0.f, a1 = 0.f, a2 = 0.f;
        for (int n = lane; n < C_; n += 32) {
            float yv  = ys[n];
            int   idx = (k * n) % C_;
            re += yv * cosT[idx];
            im -= yv * sinT[idx];                 // exp(-i*theta)
            a1 += yv * Ws1[k * C_ + n];
            a2 += yv * Ws2[k * C_ + n];
        }
#pragma unroll
        for (int o = 16; o > 0; o >>= 1) {
            re += __shfl_down_sync(0xffffffffu, re, o);
            im += __shfl_down_sync(0xffffffffu, im, o);
            a1 += __shfl_down_sync(0xffffffffu, a1, o);
            a2 += __shfl_down_sync(0xffffffffu, a2, o);
        }
        if (lane == 0) {
            float s1  = fmaxf(a1 + bs1[k], 0.f);
            float s2  = fmaxf(a2 + bs2[k], 0.f);
            float amp = sqrtf(re * re + im * im) * s1;
            float ph  = atan2f(im, re) * s2;
            float sp, cp;
            sincosf(ph, &sp, &cp);
            rRe[k] = amp * cp;
            rIm[k] = amp * sp;
        }
    }
    __syncthreads();

    // irfft (n=384) + final multiply  -- thread per output channel n=t
    {
        float acc = rRe[0];
        int   idx = 0;                 // (k*t) mod 384, by recurrence
#pragma unroll 4
        for (int k = 1; k < 192; ++k) {
            idx += t;
            if (idx >= C_) idx -= C_;
            acc += 2.f * (rRe[k] * cosT[idx] - rIm[k] * sinT[idx]);
        }
        float c192 = (t & 1) ? -1.f : 1.f;     // cos(pi*n)
        acc += rRe[192] * c192;
        float xr = acc * (1.f / (float)C_);
        out[b * C_ + t] = xr * ys[t];
    }
}

// ---------------------------------------------------------------------------
extern "C" void kernel_launch(void* const* d_in, const int* in_sizes, int n_in,
                              void* d_out, int out_size) {
    const float* x   = (const float*)d_in[0];
    const float* W1  = (const float*)d_in[1];
    const float* b1  = (const float*)d_in[2];
    const float* W2  = (const float*)d_in[3];
    const float* b2  = (const float*)d_in[4];
    const float* Ws1 = (const float*)d_in[5];
    const float* bs1 = (const float*)d_in[6];
    const float* Ws2 = (const float*)d_in[7];
    const float* bs2 = (const float*)d_in[8];
    float* out = (float*)d_out;

    pool_kernel<<<B_ * C_, 256>>>(x);
    head_kernel<<<B_, C_>>>(W1, b1, W2, b2, Ws1, bs1, Ws2, bs2, out);
}

// round 2
// speedup vs baseline: 1.7514x; 1.7514x over previous
#include <cuda_runtime.h>
#include <math.h>

#define B_   16
#define C_   384
#define CH_  64
#define CF_  193
#define HW_  16384   // 128*128

__device__ float g_y0[B_ * C_];    // pooled means
__device__ float g_ys[B_ * C_];    // sigmoid gate y
__device__ float g_rRe[B_ * CF_];  // spectral re
__device__ float g_rIm[B_ * CF_];  // spectral im

// ---------------------------------------------------------------------------
// Kernel 1: global average pool. One block per (b,c). 256 threads, float4.
// (measured ~54us = ~7.4TB/s, at HBM roofline)
// ---------------------------------------------------------------------------
__global__ __launch_bounds__(256) void pool_kernel(const float* __restrict__ x) {
    const int bc = blockIdx.x;
    const float4* __restrict__ p =
        reinterpret_cast<const float4*>(x + (size_t)bc * HW_);
    float s = 0.f;
#pragma unroll
    for (int i = 0; i < 16; ++i) {
        float4 v = p[threadIdx.x + 256 * i];
        s += (v.x + v.y) + (v.z + v.w);
    }
#pragma unroll
    for (int o = 16; o > 0; o >>= 1) s += __shfl_down_sync(0xffffffffu, s, o);
    __shared__ float ws[8];
    if ((threadIdx.x & 31) == 0) ws[threadIdx.x >> 5] = s;
    __syncthreads();
    if (threadIdx.x < 8) {
        s = ws[threadIdx.x];
#pragma unroll
        for (int o = 4; o > 0; o >>= 1) s += __shfl_down_sync(0xffu, s, o);
        if (threadIdx.x == 0) g_y0[bc] = s * (1.f / (float)HW_);
    }
}

// ---------------------------------------------------------------------------
// Kernel 2: SE gate. One block per batch, 384 threads.
//   h = relu(y0 @ W1c^T + b1);  y = sigmoid(h @ W2c^T + b2)
// ---------------------------------------------------------------------------
__global__ __launch_bounds__(384) void k_y(
    const float* __restrict__ W1, const float* __restrict__ b1,
    const float* __restrict__ W2, const float* __restrict__ b2)
{
    const int b    = blockIdx.x;
    const int t    = threadIdx.x;
    const int w    = t >> 5;
    const int lane = t & 31;

    __shared__ float y0s[C_];
    __shared__ float hs[CH_];

    y0s[t] = g_y0[b * C_ + t];
    __syncthreads();

    for (int j = w; j < CH_; j += 12) {
        float acc = 0.f;
        for (int n = lane; n < C_; n += 32)
            acc += y0s[n] * W1[j * (C_ * 9) + n * 9 + 4];
#pragma unroll
        for (int o = 16; o > 0; o >>= 1) acc += __shfl_down_sync(0xffffffffu, acc, o);
        if (lane == 0) hs[j] = fmaxf(acc + b1[j], 0.f);
    }
    __syncthreads();

    {
        float acc = 0.f;
#pragma unroll
        for (int j = 0; j < CH_; ++j)
            acc += hs[j] * W2[t * (CH_ * 9) + j * 9 + 4];
        acc += b2[t];
        g_ys[b * C_ + t] = 1.f / (1.f + expf(-acc));
    }
}

// ---------------------------------------------------------------------------
// Kernel 3: spectral bins. One warp per (b,k): 16*193 = 3088 warps.
//   re/im = DFT_k(y);  a1/a2 = Ws1/Ws2 matvec rows;  amp/phase rescale.
// ---------------------------------------------------------------------------
__global__ __launch_bounds__(256) void k_spec(
    const float* __restrict__ Ws1, const float* __restrict__ bs1,
    const float* __restrict__ Ws2, const float* __restrict__ bs2)
{
    const int wid  = blockIdx.x * 8 + (threadIdx.x >> 5);
    const int lane = threadIdx.x & 31;
    if (wid >= B_ * CF_) return;
    const int b = wid / CF_;
    const int k = wid - b * CF_;

    const float* __restrict__ yrow = g_ys + b * C_;
    float re = 0.f, im = 0.f, a1 = 0.f, a2 = 0.f;
#pragma unroll
    for (int i = 0; i < 12; ++i) {
        int   n  = lane + 32 * i;
        float yv = yrow[n];
        int   m  = (k * n) % C_;
        float sv, cv;
        sincosf((float)m * (6.283185307179586f / (float)C_), &sv, &cv);
        re += yv * cv;
        im -= yv * sv;
        a1 += yv * Ws1[k * C_ + n];
        a2 += yv * Ws2[k * C_ + n];
    }
#pragma unroll
    for (int o = 16; o > 0; o >>= 1) {
        re += __shfl_down_sync(0xffffffffu, re, o);
        im += __shfl_down_sync(0xffffffffu, im, o);
        a1 += __shfl_down_sync(0xffffffffu, a1, o);
        a2 += __shfl_down_sync(0xffffffffu, a2, o);
    }
    if (lane == 0) {
        float s1  = fmaxf(a1 + bs1[k], 0.f);
        float s2  = fmaxf(a2 + bs2[k], 0.f);
        float amp = sqrtf(re * re + im * im) * s1;
        float ph  = atan2f(im, re) * s2;
        float sp, cp;
        sincosf(ph, &sp, &cp);
        g_rRe[wid] = amp * cp;
        g_rIm[wid] = amp * sp;
    }
}

// ---------------------------------------------------------------------------
// Kernel 4: irfft(n=384) + final gate multiply. One warp per (b,n):
// 16*384 = 6144 warps. Lane handles k = 1+lane, 33+lane, ... (6 terms).
// xr[n] = (rRe0 + sum_{k=1}^{191} 2(rRe_k cos - rIm_k sin) + rRe192*(-1)^n)/384
// ---------------------------------------------------------------------------
__global__ __launch_bounds__(256) void k_irfft(float* __restrict__ out)
{
    const int wid  = blockIdx.x * 8 + (threadIdx.x >> 5);
    const int lane = threadIdx.x & 31;
    if (wid >= B_ * C_) return;
    const int b = wid / C_;
    const int n = wid - b * C_;

    const float* __restrict__ rRe = g_rRe + b * CF_;
    const float* __restrict__ rIm = g_rIm + b * CF_;

    float acc = 0.f;
#pragma unroll
    for (int i = 0; i < 6; ++i) {
        int   k   = 1 + lane + 32 * i;          // 1..192
        float wgt = (k == 192) ? 1.f : 2.f;
        int   m   = (k * n) % C_;
        float sv, cv;
        sincosf((float)m * (6.283185307179586f / (float)C_), &sv, &cv);
        acc += wgt * (rRe[k] * cv - rIm[k] * sv);
    }
#pragma unroll
    for (int o = 16; o > 0; o >>= 1) acc += __shfl_down_sync(0xffffffffu, acc, o);
    if (lane == 0) {
        float xr = (acc + rRe[0]) * (1.f / (float)C_);
        out[wid] = xr * g_ys[wid];
    }
}

// ---------------------------------------------------------------------------
extern "C" void kernel_launch(void* const* d_in, const int* in_sizes, int n_in,
                              void* d_out, int out_size) {
    const float* x   = (const float*)d_in[0];
    const float* W1  = (const float*)d_in[1];
    const float* b1  = (const float*)d_in[2];
    const float* W2  = (const float*)d_in[3];
    const float* b2  = (const float*)d_in[4];
    const float* Ws1 = (const float*)d_in[5];
    const float* bs1 = (const float*)d_in[6];
    const float* Ws2 = (const float*)d_in[7];
    const float* bs2 = (const float*)d_in[8];
    float* out = (float*)d_out;

    pool_kernel<<<B_ * C_, 256>>>(x);
    k_y<<<B_, C_>>>(W1, b1, W2, b2);
    k_spec<<<(B_ * CF_ + 7) / 8, 256>>>(Ws1, bs1, Ws2, bs2);
    k_irfft<<<(B_ * C_ + 7) / 8, 256>>>(out);
}

// round 3
// speedup vs baseline: 2.0458x; 1.1681x over previous
#include <cuda_runtime.h>
#include <math.h>

#define B_   16
#define C_   384
#define CH_  64
#define CF_  193
#define HW_  16384   // 128*128

__device__ float g_y0[B_ * C_];    // pooled means
__device__ float g_h [B_ * CH_];   // hidden relu
__device__ float g_ys[B_ * C_];    // sigmoid gate y
__device__ float g_rRe[B_ * CF_];  // spectral re
__device__ float g_rIm[B_ * CF_];  // spectral im
__device__ float g_cos[C_];        // twiddle table cos(2*pi*m/384)
__device__ float g_sin[C_];

// ---------------------------------------------------------------------------
// Kernel 1: global average pool. One block per (b,c). 256 threads, float4.
// (~54us = ~7.4TB/s, at HBM roofline). Block 0 also builds the twiddle table
// on otherwise-idle ALUs.
// ---------------------------------------------------------------------------
__global__ __launch_bounds__(256) void pool_kernel(const float* __restrict__ x) {
    if (blockIdx.x == 0) {
        for (int m = threadIdx.x; m < C_; m += 256) {
            float sv, cv;
            sincosf((float)m * (6.283185307179586f / (float)C_), &sv, &cv);
            g_cos[m] = cv;
            g_sin[m] = sv;
        }
    }
    const int bc = blockIdx.x;
    const float4* __restrict__ p =
        reinterpret_cast<const float4*>(x + (size_t)bc * HW_);
    float s = 0.f;
#pragma unroll
    for (int i = 0; i < 16; ++i) {
        float4 v = p[threadIdx.x + 256 * i];
        s += (v.x + v.y) + (v.z + v.w);
    }
#pragma unroll
    for (int o = 16; o > 0; o >>= 1) s += __shfl_down_sync(0xffffffffu, s, o);
    __shared__ float ws[8];
    if ((threadIdx.x & 31) == 0) ws[threadIdx.x >> 5] = s;
    __syncthreads();
    if (threadIdx.x < 8) {
        s = ws[threadIdx.x];
#pragma unroll
        for (int o = 4; o > 0; o >>= 1) s += __shfl_down_sync(0xffu, s, o);
        if (threadIdx.x == 0) g_y0[bc] = s * (1.f / (float)HW_);
    }
}

// ---------------------------------------------------------------------------
// Kernel 2: h[b,j] = relu(sum_c y0[b,c]*W1[j,c,1,1] + b1[j]).
// One warp per (b,j): 1024 warps, 128 blocks.
// ---------------------------------------------------------------------------
__global__ __launch_bounds__(256) void k_h(
    const float* __restrict__ W1, const float* __restrict__ b1)
{
    const int wid  = blockIdx.x * 8 + (threadIdx.x >> 5);   // 0..1023
    const int lane = threadIdx.x & 31;
    const int b = wid >> 6;
    const int j = wid & 63;
    const float* __restrict__ y0 = g_y0 + b * C_;
    float acc = 0.f;
#pragma unroll
    for (int i = 0; i < 12; ++i) {
        int n = lane + 32 * i;
        acc += y0[n] * W1[j * (C_ * 9) + n * 9 + 4];
    }
#pragma unroll
    for (int o = 16; o > 0; o >>= 1) acc += __shfl_down_sync(0xffffffffu, acc, o);
    if (lane == 0) g_h[wid] = fmaxf(acc + b1[j], 0.f);
}

// ---------------------------------------------------------------------------
// Kernel 3: y[b,c] = sigmoid(sum_j h[b,j]*W2[c,j,1,1] + b2[c]).
// One thread per (b,c): 6144 threads, 24 blocks.
// ---------------------------------------------------------------------------
__global__ __launch_bounds__(256) void k_gate(
    const float* __restrict__ W2, const float* __restrict__ b2)
{
    const int bc = blockIdx.x * 256 + threadIdx.x;
    const int b = bc / C_;
    const int c = bc - b * C_;
    const float* __restrict__ h = g_h + b * CH_;
    float acc = b2[c];
#pragma unroll
    for (int j = 0; j < CH_; ++j)
        acc += h[j] * W2[c * (CH_ * 9) + j * 9 + 4];
    g_ys[bc] = 1.f / (1.f + expf(-acc));
}

// ---------------------------------------------------------------------------
// Kernel 4: spectral bins. Block = one b x 8 bins (grid 16*25=400).
// Shared y row + twiddle tables; warp per bin k.
// ---------------------------------------------------------------------------
__global__ __launch_bounds__(256) void k_spec(
    const float* __restrict__ Ws1, const float* __restrict__ bs1,
    const float* __restrict__ Ws2, const float* __restrict__ bs2)
{
    const int b  = blockIdx.x / 25;
    const int kg = blockIdx.x - b * 25;
    const int t  = threadIdx.x;
    const int lane = t & 31;

    __shared__ float ys[C_], cT[C_], sT[C_];
    for (int m = t; m < C_; m += 256) {
        ys[m] = g_ys[b * C_ + m];
        cT[m] = g_cos[m];
        sT[m] = g_sin[m];
    }
    __syncthreads();

    const int k = kg * 8 + (t >> 5);
    if (k >= CF_) return;

    float re = 0.f, im = 0.f, a1 = 0.f, a2 = 0.f;
#pragma unroll
    for (int i = 0; i < 12; ++i) {
        int   n  = lane + 32 * i;
        float yv = ys[n];
        int   m  = (k * n) % C_;
        re += yv * cT[m];
        im -= yv * sT[m];
        a1 += yv * Ws1[k * C_ + n];
        a2 += yv * Ws2[k * C_ + n];
    }
#pragma unroll
    for (int o = 16; o > 0; o >>= 1) {
        re += __shfl_down_sync(0xffffffffu, re, o);
        im += __shfl_down_sync(0xffffffffu, im, o);
        a1 += __shfl_down_sync(0xffffffffu, a1, o);
        a2 += __shfl_down_sync(0xffffffffu, a2, o);
    }
    if (lane == 0) {
        float s1  = fmaxf(a1 + bs1[k], 0.f);
        float s2  = fmaxf(a2 + bs2[k], 0.f);
        float amp = sqrtf(re * re + im * im) * s1;
        float ph  = atan2f(im, re) * s2;
        float sp, cp;
        sincosf(ph, &sp, &cp);
        g_rRe[b * CF_ + k] = amp * cp;
        g_rIm[b * CF_ + k] = amp * sp;
    }
}

// ---------------------------------------------------------------------------
// Kernel 5: irfft(n=384) + gate multiply. Block = one b x 8 outputs
// (grid 16*48=768). Shared spectrum + tables; warp per output n.
// xr[n] = (rRe0 + sum_{k=1}^{191} 2(rRe_k cos - rIm_k sin) + rRe192*(-1)^n)/384
// ---------------------------------------------------------------------------
__global__ __launch_bounds__(256) void k_irfft(float* __restrict__ out)
{
    const int b  = blockIdx.x / 48;
    const int ng = blockIdx.x - b * 48;
    const int t  = threadIdx.x;
    const int lane = t & 31;

    __shared__ float sRe[CF_], sIm[CF_], cT[C_], sT[C_];
    for (int m = t; m < C_; m += 256) {
        cT[m] = g_cos[m];
        sT[m] = g_sin[m];
    }
    for (int m = t; m < CF_; m += 256) {
        sRe[m] = g_rRe[b * CF_ + m];
        sIm[m] = g_rIm[b * CF_ + m];
    }
    __syncthreads();

    const int n = ng * 8 + (t >> 5);

    float acc = 0.f;
#pragma unroll
    for (int i = 0; i < 6; ++i) {
        int   k   = 1 + lane + 32 * i;          // 1..192
        float wgt = (k == 192) ? 1.f : 2.f;
        int   m   = (k * n) % C_;
        acc += wgt * (sRe[k] * cT[m] - sIm[k] * sT[m]);
    }
#pragma unroll
    for (int o = 16; o > 0; o >>= 1) acc += __shfl_down_sync(0xffffffffu, acc, o);
    if (lane == 0) {
        float xr = (acc + sRe[0]) * (1.f / (float)C_);
        out[b * C_ + n] = xr * g_ys[b * C_ + n];
    }
}

// ---------------------------------------------------------------------------
extern "C" void kernel_launch(void* const* d_in, const int* in_sizes, int n_in,
                              void* d_out, int out_size) {
    const float* x   = (const float*)d_in[0];
    const float* W1  = (const float*)d_in[1];
    const float* b1  = (const float*)d_in[2];
    const float* W2  = (const float*)d_in[3];
    const float* b2  = (const float*)d_in[4];
    const float* Ws1 = (const float*)d_in[5];
    const float* bs1 = (const float*)d_in[6];
    const float* Ws2 = (const float*)d_in[7];
    const float* bs2 = (const float*)d_in[8];
    float* out = (float*)d_out;

    pool_kernel<<<B_ * C_, 256>>>(x);
    k_h<<<B_ * CH_ / 8, 256>>>(W1, b1);
    k_gate<<<B_ * C_ / 256, 256>>>(W2, b2);
    k_spec<<<B_ * 25, 256>>>(Ws1, bs1, Ws2, bs2);
    k_irfft<<<B_ * 48, 256>>>(out);
}